// round 10
// baseline (speedup 1.0000x reference)
#include <cuda_runtime.h>
#include <cuda_fp16.h>
#include <cuda_bf16.h>
#include <cstdint>

// KANLayer: out[b] = sum_{d,h} tanh(x[b,d]*w1[d,h] + b1[d,h]) * w2[d,h] + sum_d b2[d]
// B=65536, D=256, H=16.
//
// 4-way row split: each row is handled by 4 consecutive lanes; lane-quad member
// p owns h in [4p, 4p+4) for all d. 262144 threads -> 8 warps/SMSP (vs 3.5
// before) to hide LDS/MUFU latency. Per 2 terms: HFMA2(f16 arg) ->
// tanh.approx.f16x2 (1 MUFU) -> 2x F2F -> 2x fp32 FFMA into fp32 accumulators
// (w2 kept fp32) -- no f16 accumulation, cutting R5's error sources.

#define D_DIM 256
#define H_DIM 16
#define DH    (D_DIM * H_DIM)   // 4096
#define B_DIM 65536
#define TPB   256               // 64 rows per block
#define ROWS_PER_BLOCK (TPB / 4)

__device__ __forceinline__ __half2 htanh2(__half2 v) {
    unsigned vi = *reinterpret_cast<unsigned*>(&v);
    unsigned ro;
    asm("tanh.approx.f16x2 %0, %1;" : "=r"(ro) : "r"(vi));
    return *reinterpret_cast<__half2*>(&ro);
}

__global__ __launch_bounds__(TPB, 4) void kan_main(const float* __restrict__ x,
                                                   const float* __restrict__ w1,
                                                   const float* __restrict__ b1,
                                                   const float* __restrict__ w2,
                                                   const float* __restrict__ b2,
                                                   float* __restrict__ out) {
    // [d][h] layouts. w1/b1 packed half2 (8KB each), w2 fp32 (16KB). 32KB total
    // -> 4 blocks/SM fits 128KB of 228KB.
    __shared__ __half2 s_w1[DH / 2];
    __shared__ __half2 s_b1[DH / 2];
    __shared__ float   s_w2[DH];
    __shared__ float   s_red[8];

    const int t    = threadIdx.x;
    const int lane = t & 31;
    const int wid  = t >> 5;
    const int p    = t & 3;        // h-quadrant within the row's lane-quad

    // ---- Sum(b2): fixed-order deterministic reduce (D=256 elems, TPB=256).
    float myb2 = b2[t];
    #pragma unroll
    for (int off = 16; off > 0; off >>= 1)
        myb2 += __shfl_xor_sync(0xFFFFFFFFu, myb2, off);
    if (lane == 0) s_red[wid] = myb2;
    __syncthreads();
    float C = 0.0f;
    #pragma unroll
    for (int i = 0; i < 8; ++i) C += s_red[i];

    // ---- Stage params ([d][h] linear; half2 packs h pairs).
    {
        const float4* gw1 = reinterpret_cast<const float4*>(w1);
        const float4* gb1 = reinterpret_cast<const float4*>(b1);
        const float4* gw2 = reinterpret_cast<const float4*>(w2);
        float4* sw2 = reinterpret_cast<float4*>(s_w2);
        #pragma unroll
        for (int i = t; i < DH / 4; i += TPB) {
            float4 a  = gw1[i];
            float4 bb = gb1[i];
            s_w1[2 * i]     = __floats2half2_rn(a.x, a.y);
            s_w1[2 * i + 1] = __floats2half2_rn(a.z, a.w);
            s_b1[2 * i]     = __floats2half2_rn(bb.x, bb.y);
            s_b1[2 * i + 1] = __floats2half2_rn(bb.z, bb.w);
            sw2[i] = gw2[i];
        }
    }
    __syncthreads();

    // ---- Row for this lane-quad. All 4 lanes read identical x addresses
    // (coalescer broadcast). Params: 4 distinct words within a 64B span per
    // warp access -> conflict-free broadcast.
    const int row = blockIdx.x * ROWS_PER_BLOCK + (t >> 2);
    const float4* xr = reinterpret_cast<const float4*>(x) + (size_t)row * (D_DIM / 4);

    float acc0 = 0.0f, acc1 = 0.0f, acc2 = 0.0f, acc3 = 0.0f;

    #pragma unroll 4
    for (int d4 = 0; d4 < D_DIM / 4; ++d4) {
        const float4 xv = xr[d4];
        #pragma unroll
        for (int j = 0; j < 4; ++j) {
            const float xd = (j == 0) ? xv.x : (j == 1) ? xv.y : (j == 2) ? xv.z : xv.w;
            const int d = d4 * 4 + j;
            const int hbase = d * (H_DIM / 2) + p * 2;   // 2 half2 = 4 h values

            // 8-byte LDS for the half2 pairs
            const uint2 w1u = *reinterpret_cast<const uint2*>(&s_w1[hbase]);
            const uint2 b1u = *reinterpret_cast<const uint2*>(&s_b1[hbase]);
            const float4 w2v = *reinterpret_cast<const float4*>(&s_w2[d * H_DIM + p * 4]);

            const __half2 w10 = *reinterpret_cast<const __half2*>(&w1u.x);
            const __half2 w11 = *reinterpret_cast<const __half2*>(&w1u.y);
            const __half2 b10 = *reinterpret_cast<const __half2*>(&b1u.x);
            const __half2 b11 = *reinterpret_cast<const __half2*>(&b1u.y);

            const __half2 xx = __float2half2_rn(xd);

            const __half2 t0 = htanh2(__hfma2(xx, w10, b10));
            const __half2 t1 = htanh2(__hfma2(xx, w11, b11));

            const float2 f0 = __half22float2(t0);
            const float2 f1 = __half22float2(t1);

            acc0 = fmaf(w2v.x, f0.x, acc0);
            acc1 = fmaf(w2v.y, f0.y, acc1);
            acc2 = fmaf(w2v.z, f1.x, acc2);
            acc3 = fmaf(w2v.w, f1.y, acc3);
        }
    }

    // ---- Combine the 4 accumulators, then the 4 lanes of the quad.
    float s = (acc0 + acc1) + (acc2 + acc3);
    s += __shfl_xor_sync(0xFFFFFFFFu, s, 1);
    s += __shfl_xor_sync(0xFFFFFFFFu, s, 2);

    if (p == 0) out[row] = s + C;
}

extern "C" void kernel_launch(void* const* d_in, const int* in_sizes, int n_in,
                              void* d_out, int out_size) {
    const float* x  = (const float*)d_in[0];
    const float* w1 = (const float*)d_in[1];
    const float* b1 = (const float*)d_in[2];
    const float* w2 = (const float*)d_in[3];
    const float* b2 = (const float*)d_in[4];
    float* out = (float*)d_out;

    kan_main<<<(B_DIM / ROWS_PER_BLOCK), TPB>>>(x, w1, b1, w2, b2, out);
}

// round 11
// speedup vs baseline: 1.1469x; 1.1469x over previous
#include <cuda_runtime.h>
#include <cuda_fp16.h>
#include <cuda_bf16.h>
#include <cstdint>

// KANLayer: out[b] = sum_{d,h} tanh(x[b,d]*w1[d,h] + b1[d,h]) * w2[d,h] + sum_d b2[d]
// B=65536, D=256, H=16.
//
// Layout: thread = (group g, quad p). Quad member p owns h in [4p,4p+4).
// Each thread processes R=2 rows, so ONE param fetch per d (LDS.128 of
// interleaved f16 w1|b1 + LDS.128 of fp32 w2) feeds 2 rows x 4 h of work.
// Per row-d (SM-normalized): MUFU 2.0 cyc (binding), param LDS 0.5, x ~0.25.
// fp32 accumulation with fp32 w2 (keeps rel_err ~5.5e-4 as in R7).

#define D_DIM 256
#define H_DIM 16
#define DH    (D_DIM * H_DIM)   // 4096
#define B_DIM 65536
#define TPB   128               // 32 quads * 2 rows = 64 rows/block
#define ROWS_PER_BLOCK 64       // grid = 1024

__device__ __forceinline__ __half2 htanh2(__half2 v) {
    unsigned vi = *reinterpret_cast<unsigned*>(&v);
    unsigned ro;
    asm("tanh.approx.f16x2 %0, %1;" : "=r"(ro) : "r"(vi));
    return *reinterpret_cast<__half2*>(&ro);
}

__global__ __launch_bounds__(TPB) void kan_main(const float* __restrict__ x,
                                                const float* __restrict__ w1,
                                                const float* __restrict__ b1,
                                                const float* __restrict__ w2,
                                                const float* __restrict__ b2,
                                                float* __restrict__ out) {
    // s_wb[d*4+p] = {w1h2(4p,4p+1), w1h2(4p+2,4p+3), b1h2(4p,4p+1), b1h2(4p+2,4p+3)}
    __shared__ uint4 s_wb[D_DIM * 4];   // 16 KB
    __shared__ float s_w2[DH];          // 16 KB
    __shared__ float s_red[4];

    const int t    = threadIdx.x;
    const int lane = t & 31;
    const int wid  = t >> 5;
    const int p    = t & 3;          // h-quadrant
    const int g    = t >> 2;         // row group [0,32)

    // ---- Sum(b2): fixed-order deterministic reduce (256 elems, 128 threads).
    float myb2 = b2[t] + b2[t + 128];
    #pragma unroll
    for (int off = 16; off > 0; off >>= 1)
        myb2 += __shfl_xor_sync(0xFFFFFFFFu, myb2, off);
    if (lane == 0) s_red[wid] = myb2;
    __syncthreads();
    float C = (s_red[0] + s_red[1]) + (s_red[2] + s_red[3]);

    // ---- Stage params: interleave w1|b1 as f16 pairs, w2 as fp32.
    {
        const float4* gw1 = reinterpret_cast<const float4*>(w1);
        const float4* gb1 = reinterpret_cast<const float4*>(b1);
        const float4* gw2 = reinterpret_cast<const float4*>(w2);
        float4* sw2 = reinterpret_cast<float4*>(s_w2);
        #pragma unroll
        for (int i = t; i < DH / 4; i += TPB) {   // i indexes (d,p) float4 groups
            float4 a  = gw1[i];
            float4 bb = gb1[i];
            __half2 w10 = __floats2half2_rn(a.x, a.y);
            __half2 w11 = __floats2half2_rn(a.z, a.w);
            __half2 b10 = __floats2half2_rn(bb.x, bb.y);
            __half2 b11 = __floats2half2_rn(bb.z, bb.w);
            uint4 packed;
            packed.x = *reinterpret_cast<unsigned*>(&w10);
            packed.y = *reinterpret_cast<unsigned*>(&w11);
            packed.z = *reinterpret_cast<unsigned*>(&b10);
            packed.w = *reinterpret_cast<unsigned*>(&b11);
            s_wb[i] = packed;
            sw2[i] = gw2[i];
        }
    }
    __syncthreads();

    // ---- Two rows per thread.
    const int row0 = blockIdx.x * ROWS_PER_BLOCK + g * 2;
    const int row1 = row0 + 1;
    const float4* xr0 = reinterpret_cast<const float4*>(x) + (size_t)row0 * (D_DIM / 4);
    const float4* xr1 = reinterpret_cast<const float4*>(x) + (size_t)row1 * (D_DIM / 4);

    float a00 = 0.f, a01 = 0.f, a02 = 0.f, a03 = 0.f;   // row0, h = 4p..4p+3
    float a10 = 0.f, a11 = 0.f, a12 = 0.f, a13 = 0.f;   // row1

    #pragma unroll 2
    for (int d4 = 0; d4 < D_DIM / 4; ++d4) {
        const float4 xv0 = xr0[d4];
        const float4 xv1 = xr1[d4];
        #pragma unroll
        for (int j = 0; j < 4; ++j) {
            const float xd0 = (j == 0) ? xv0.x : (j == 1) ? xv0.y : (j == 2) ? xv0.z : xv0.w;
            const float xd1 = (j == 0) ? xv1.x : (j == 1) ? xv1.y : (j == 2) ? xv1.z : xv1.w;
            const int d = d4 * 4 + j;

            const uint4  wb  = s_wb[d * 4 + p];
            const float4 w2v = *reinterpret_cast<const float4*>(&s_w2[d * H_DIM + p * 4]);

            const __half2 w10 = *reinterpret_cast<const __half2*>(&wb.x);
            const __half2 w11 = *reinterpret_cast<const __half2*>(&wb.y);
            const __half2 b10 = *reinterpret_cast<const __half2*>(&wb.z);
            const __half2 b11 = *reinterpret_cast<const __half2*>(&wb.w);

            const __half2 xx0 = __float2half2_rn(xd0);
            const __half2 xx1 = __float2half2_rn(xd1);

            const __half2 t00 = htanh2(__hfma2(xx0, w10, b10));
            const __half2 t01 = htanh2(__hfma2(xx0, w11, b11));
            const __half2 t10 = htanh2(__hfma2(xx1, w10, b10));
            const __half2 t11 = htanh2(__hfma2(xx1, w11, b11));

            const float2 f00 = __half22float2(t00);
            const float2 f01 = __half22float2(t01);
            const float2 f10 = __half22float2(t10);
            const float2 f11 = __half22float2(t11);

            a00 = fmaf(w2v.x, f00.x, a00);
            a01 = fmaf(w2v.y, f00.y, a01);
            a02 = fmaf(w2v.z, f01.x, a02);
            a03 = fmaf(w2v.w, f01.y, a03);

            a10 = fmaf(w2v.x, f10.x, a10);
            a11 = fmaf(w2v.y, f10.y, a11);
            a12 = fmaf(w2v.z, f11.x, a12);
            a13 = fmaf(w2v.w, f11.y, a13);
        }
    }

    // ---- Combine 4 accumulators per row, then the 4 lanes of the quad.
    float s0 = (a00 + a01) + (a02 + a03);
    float s1 = (a10 + a11) + (a12 + a13);
    s0 += __shfl_xor_sync(0xFFFFFFFFu, s0, 1);
    s0 += __shfl_xor_sync(0xFFFFFFFFu, s0, 2);
    s1 += __shfl_xor_sync(0xFFFFFFFFu, s1, 1);
    s1 += __shfl_xor_sync(0xFFFFFFFFu, s1, 2);

    if (p == 0) {
        out[row0] = s0 + C;
        out[row1] = s1 + C;
    }
}

extern "C" void kernel_launch(void* const* d_in, const int* in_sizes, int n_in,
                              void* d_out, int out_size) {
    const float* x  = (const float*)d_in[0];
    const float* w1 = (const float*)d_in[1];
    const float* b1 = (const float*)d_in[2];
    const float* w2 = (const float*)d_in[3];
    const float* b2 = (const float*)d_in[4];
    float* out = (float*)d_out;

    kan_main<<<B_DIM / ROWS_PER_BLOCK, TPB>>>(x, w1, b1, w2, b2, out);
}

// round 15
// speedup vs baseline: 1.1782x; 1.0273x over previous
#include <cuda_runtime.h>
#include <cuda_fp16.h>
#include <cuda_bf16.h>
#include <cstdint>

// KANLayer: out[b] = sum_{d,h} tanh(x[b,d]*w1[d,h] + b1[d,h]) * w2[d,h] + sum_d b2[d]
// B=65536, D=256, H=16.
//
// R10 layout (quad h-split, 2 rows/thread, params in smem) + cp.async
// double-buffered x staging so DRAM latency is structurally hidden:
// tile = 16 d x 64 rows staged into smem while the previous tile computes.
// Inner loop reads x via LDS.128 (29 cyc, ILP-hidden) instead of raw LDG
// (577 cyc exposed). Arithmetic identical to R10 (f16x2 args+tanh, fp32
// w2/accumulate) -> rel_err unchanged.

#define D_DIM 256
#define H_DIM 16
#define DH    (D_DIM * H_DIM)   // 4096
#define B_DIM 65536
#define TPB   128               // 32 quads * 2 rows = 64 rows/block
#define ROWS_PER_BLOCK 64       // grid = 1024
#define TILE_D 16               // d-values per x tile
#define NT (D_DIM / TILE_D)     // 16 tiles
#define XPITCH (TILE_D + 4)     // 20 floats = 80B pitch (16B aligned, staggers banks)

__device__ __forceinline__ __half2 htanh2(__half2 v) {
    unsigned vi = *reinterpret_cast<unsigned*>(&v);
    unsigned ro;
    asm("tanh.approx.f16x2 %0, %1;" : "=r"(ro) : "r"(vi));
    return *reinterpret_cast<__half2*>(&ro);
}

__device__ __forceinline__ void cp_async16(void* sdst, const void* gsrc) {
    uint32_t s = (uint32_t)__cvta_generic_to_shared(sdst);
    asm volatile("cp.async.cg.shared.global [%0], [%1], 16;" :: "r"(s), "l"(gsrc));
}
__device__ __forceinline__ void cp_commit() {
    asm volatile("cp.async.commit_group;");
}
template <int N> __device__ __forceinline__ void cp_wait() {
    asm volatile("cp.async.wait_group %0;" :: "n"(N));
}

__global__ __launch_bounds__(TPB) void kan_main(const float* __restrict__ x,
                                                const float* __restrict__ w1,
                                                const float* __restrict__ b1,
                                                const float* __restrict__ w2,
                                                const float* __restrict__ b2,
                                                float* __restrict__ out) {
    // s_wb[d*4+p] = {w1h2(4p,4p+1), w1h2(4p+2,4p+3), b1h2(4p,4p+1), b1h2(4p+2,4p+3)}
    __shared__ uint4 s_wb[D_DIM * 4];                      // 16 KB
    __shared__ float s_w2[DH];                             // 16 KB
    __shared__ float s_x[2][ROWS_PER_BLOCK][XPITCH];       // 10.25 KB
    __shared__ float s_red[4];
    // total ~42.3 KB static (< 48 KB cap) -> 5 blocks/SM

    const int t    = threadIdx.x;
    const int lane = t & 31;
    const int wid  = t >> 5;
    const int p    = t & 3;          // h-quadrant
    const int g    = t >> 2;         // row group [0,32)

    // ---- Sum(b2): fixed-order deterministic reduce (256 elems, 128 threads).
    float myb2 = b2[t] + b2[t + 128];
    #pragma unroll
    for (int off = 16; off > 0; off >>= 1)
        myb2 += __shfl_xor_sync(0xFFFFFFFFu, myb2, off);
    if (lane == 0) s_red[wid] = myb2;
    __syncthreads();
    const float C = (s_red[0] + s_red[1]) + (s_red[2] + s_red[3]);

    // ---- Stage params: interleave w1|b1 as f16 pairs, w2 as fp32.
    {
        const float4* gw1 = reinterpret_cast<const float4*>(w1);
        const float4* gb1 = reinterpret_cast<const float4*>(b1);
        const float4* gw2 = reinterpret_cast<const float4*>(w2);
        float4* sw2 = reinterpret_cast<float4*>(s_w2);
        #pragma unroll
        for (int i = t; i < DH / 4; i += TPB) {
            float4 a  = gw1[i];
            float4 bb = gb1[i];
            __half2 w10 = __floats2half2_rn(a.x, a.y);
            __half2 w11 = __floats2half2_rn(a.z, a.w);
            __half2 b10 = __floats2half2_rn(bb.x, bb.y);
            __half2 b11 = __floats2half2_rn(bb.z, bb.w);
            uint4 packed;
            packed.x = *reinterpret_cast<unsigned*>(&w10);
            packed.y = *reinterpret_cast<unsigned*>(&w11);
            packed.z = *reinterpret_cast<unsigned*>(&b10);
            packed.w = *reinterpret_cast<unsigned*>(&b11);
            s_wb[i] = packed;
            sw2[i] = gw2[i];
        }
    }

    const int row_base = blockIdx.x * ROWS_PER_BLOCK;

    // ---- x tile loader: 64 rows x 16 d = 4 KB -> 256 x 16B chunks, 2/thread.
    // Warp-coalesced: 4 consecutive rows x 64B contiguous per warp-issue.
    auto load_tile = [&](int tile, int buf) {
        #pragma unroll
        for (int i = 0; i < 2; ++i) {
            const int chunk = t + i * TPB;        // [0,256)
            const int rowL  = chunk >> 2;
            const int c     = chunk & 3;
            cp_async16(&s_x[buf][rowL][c * 4],
                       x + (size_t)(row_base + rowL) * D_DIM + tile * TILE_D + c * 4);
        }
        cp_commit();
    };

    load_tile(0, 0);
    __syncthreads();   // param staging visible before compute

    const int r0L = g * 2;
    const int r1L = g * 2 + 1;

    float a00 = 0.f, a01 = 0.f, a02 = 0.f, a03 = 0.f;   // row0, h = 4p..4p+3
    float a10 = 0.f, a11 = 0.f, a12 = 0.f, a13 = 0.f;   // row1

    for (int tile = 0; tile < NT; ++tile) {
        const int buf = tile & 1;
        if (tile + 1 < NT) {
            load_tile(tile + 1, buf ^ 1);
            cp_wait<1>();    // tile's data landed (one newer group pending)
        } else {
            cp_wait<0>();
        }
        __syncthreads();

        const int dbase = tile * TILE_D;
        #pragma unroll
        for (int q4 = 0; q4 < TILE_D / 4; ++q4) {
            const float4 xv0 = *reinterpret_cast<const float4*>(&s_x[buf][r0L][q4 * 4]);
            const float4 xv1 = *reinterpret_cast<const float4*>(&s_x[buf][r1L][q4 * 4]);
            #pragma unroll
            for (int j = 0; j < 4; ++j) {
                const float xd0 = (j == 0) ? xv0.x : (j == 1) ? xv0.y : (j == 2) ? xv0.z : xv0.w;
                const float xd1 = (j == 0) ? xv1.x : (j == 1) ? xv1.y : (j == 2) ? xv1.z : xv1.w;
                const int d = dbase + q4 * 4 + j;

                const uint4  wb  = s_wb[d * 4 + p];
                const float4 w2v = *reinterpret_cast<const float4*>(&s_w2[d * H_DIM + p * 4]);

                const __half2 w10 = *reinterpret_cast<const __half2*>(&wb.x);
                const __half2 w11 = *reinterpret_cast<const __half2*>(&wb.y);
                const __half2 b10 = *reinterpret_cast<const __half2*>(&wb.z);
                const __half2 b11 = *reinterpret_cast<const __half2*>(&wb.w);

                const __half2 xx0 = __float2half2_rn(xd0);
                const __half2 xx1 = __float2half2_rn(xd1);

                const __half2 t00 = htanh2(__hfma2(xx0, w10, b10));
                const __half2 t01 = htanh2(__hfma2(xx0, w11, b11));
                const __half2 t10 = htanh2(__hfma2(xx1, w10, b10));
                const __half2 t11 = htanh2(__hfma2(xx1, w11, b11));

                const float2 f00 = __half22float2(t00);
                const float2 f01 = __half22float2(t01);
                const float2 f10 = __half22float2(t10);
                const float2 f11 = __half22float2(t11);

                a00 = fmaf(w2v.x, f00.x, a00);
                a01 = fmaf(w2v.y, f00.y, a01);
                a02 = fmaf(w2v.z, f01.x, a02);
                a03 = fmaf(w2v.w, f01.y, a03);

                a10 = fmaf(w2v.x, f10.x, a10);
                a11 = fmaf(w2v.y, f10.y, a11);
                a12 = fmaf(w2v.z, f11.x, a12);
                a13 = fmaf(w2v.w, f11.y, a13);
            }
        }
        __syncthreads();   // all threads done with buf before it is refilled
    }

    // ---- Combine 4 accumulators per row, then the 4 lanes of the quad.
    float s0 = (a00 + a01) + (a02 + a03);
    float s1 = (a10 + a11) + (a12 + a13);
    s0 += __shfl_xor_sync(0xFFFFFFFFu, s0, 1);
    s0 += __shfl_xor_sync(0xFFFFFFFFu, s0, 2);
    s1 += __shfl_xor_sync(0xFFFFFFFFu, s1, 1);
    s1 += __shfl_xor_sync(0xFFFFFFFFu, s1, 2);

    if (p == 0) {
        const int row0 = row_base + g * 2;
        out[row0]     = s0 + C;
        out[row0 + 1] = s1 + C;
    }
}

extern "C" void kernel_launch(void* const* d_in, const int* in_sizes, int n_in,
                              void* d_out, int out_size) {
    const float* x  = (const float*)d_in[0];
    const float* w1 = (const float*)d_in[1];
    const float* b1 = (const float*)d_in[2];
    const float* w2 = (const float*)d_in[3];
    const float* b2 = (const float*)d_in[4];
    float* out = (float*)d_out;

    kan_main<<<B_DIM / ROWS_PER_BLOCK, TPB>>>(x, w1, b1, w2, b2, out);
}